// round 3
// baseline (speedup 1.0000x reference)
#include <cuda_runtime.h>
#include <cuda_fp16.h>
#include <cuda.h>
#include <cstdint>

// Shape: M=8192 (B=4,S=2048), K=4096, N=11008
// Harness dtypes: x f32, qweight i32, scales f32, qzeros i32, out f32.
#define MTOT 8192
#define KTOT 4096
#define NTOT 11008
#define K2TOT (KTOT / 2)

// GEMM tiling (mma.sync path; tcgen05 is 'a'-gated, ptxas targets compute_103)
#define BM 128
#define BN 128
#define BK 64
#define STAGES 6
#define KTILES (KTOT / BK)          // 64
#define A_ST_BYTES (BM * BK * 2)    // 16384
#define B_ST_BYTES (BN * BK * 2)    // 16384

// SMEM layout
#define OFF_FULL 0
#define OFF_EMPTY (8 * STAGES)
#define OFF_A 1024
#define OFF_B (OFF_A + STAGES * A_ST_BYTES)
#define SMEM_TOTAL (OFF_B + STAGES * B_ST_BYTES)   // 197632

// Scratch: dequantized transposed weights Wt[N][K] (90MB) + f16 copy of x (64MB)
__device__ __align__(1024) __half g_Wt[(size_t)NTOT * KTOT];
__device__ __align__(1024) __half g_xh[(size_t)MTOT * KTOT];

// ---------------------------------------------------------------------------
// helpers
// ---------------------------------------------------------------------------
__device__ __forceinline__ uint32_t smem_u32(const void* p) {
    uint32_t a;
    asm("{ .reg .u64 t; cvta.to.shared.u64 t, %1; cvt.u32.u64 %0, t; }"
        : "=r"(a) : "l"(p));
    return a;
}

__device__ __forceinline__ void mbar_init(uint32_t mbar, uint32_t count) {
    asm volatile("mbarrier.init.shared.b64 [%0], %1;" :: "r"(mbar), "r"(count) : "memory");
}

__device__ __forceinline__ void mbar_expect_tx(uint32_t mbar, uint32_t bytes) {
    asm volatile("mbarrier.arrive.expect_tx.shared.b64 _, [%0], %1;"
                 :: "r"(mbar), "r"(bytes) : "memory");
}

__device__ __forceinline__ void mbar_arrive(uint32_t mbar) {
    asm volatile("mbarrier.arrive.shared.b64 _, [%0];" :: "r"(mbar) : "memory");
}

__device__ __forceinline__ void mbar_wait(uint32_t mbar, uint32_t parity) {
    asm volatile(
        "{\n\t"
        ".reg .pred P;\n\t"
        "WLOOP_%=:\n\t"
        "mbarrier.try_wait.parity.acquire.cta.shared::cta.b64 P, [%0], %1, 0x989680;\n\t"
        "@P bra.uni WDONE_%=;\n\t"
        "bra.uni WLOOP_%=;\n\t"
        "WDONE_%=:\n\t"
        "}"
        :: "r"(mbar), "r"(parity) : "memory");
}

__device__ __forceinline__ void tma_load_2d(uint32_t smem_dst, const void* map,
                                            int cx, int cy, uint32_t mbar) {
    asm volatile(
        "cp.async.bulk.tensor.2d.shared::cta.global.tile.mbarrier::complete_tx::bytes "
        "[%0], [%1, {%2, %3}], [%4];"
        :: "r"(smem_dst), "l"(map), "r"(cx), "r"(cy), "r"(mbar) : "memory");
}

__device__ __forceinline__ void ldsm_x4(uint32_t& r0, uint32_t& r1, uint32_t& r2,
                                        uint32_t& r3, uint32_t addr) {
    asm volatile("ldmatrix.sync.aligned.m8n8.x4.shared.b16 {%0,%1,%2,%3}, [%4];"
                 : "=r"(r0), "=r"(r1), "=r"(r2), "=r"(r3) : "r"(addr));
}

__device__ __forceinline__ void mma16816(float* c, const uint32_t* a, const uint32_t* b) {
    asm volatile(
        "mma.sync.aligned.m16n8k16.row.col.f32.f16.f16.f32 "
        "{%0,%1,%2,%3}, {%4,%5,%6,%7}, {%8,%9}, {%0,%1,%2,%3};"
        : "+f"(c[0]), "+f"(c[1]), "+f"(c[2]), "+f"(c[3])
        : "r"(a[0]), "r"(a[1]), "r"(a[2]), "r"(a[3]), "r"(b[0]), "r"(b[1]));
}

// ---------------------------------------------------------------------------
// Kernel 0: x f32 -> f16 (lossless: f32 values are exact f16 upcasts)
// ---------------------------------------------------------------------------
__global__ void __launch_bounds__(256) convert_kernel(
    const float4* __restrict__ xin, __half* __restrict__ xh) {
    const size_t i = (size_t)blockIdx.x * 256 + threadIdx.x;  // one float4 each
    float4 v = xin[i];
    __half2 lo = __floats2half2_rn(v.x, v.y);
    __half2 hi = __floats2half2_rn(v.z, v.w);
    uint2 pack;
    pack.x = *reinterpret_cast<uint32_t*>(&lo);
    pack.y = *reinterpret_cast<uint32_t*>(&hi);
    *reinterpret_cast<uint2*>(&xh[4 * i]) = pack;
}

// ---------------------------------------------------------------------------
// Kernel 1: dequant + transpose  qweight[K/2,N] i32, scales[K/128,N] f32,
//           qzeros[K/256,N] i32  ->  Wt[N,K] fp16
// ---------------------------------------------------------------------------
__global__ void __launch_bounds__(256) dequant_kernel(
    const int* __restrict__ qw, const float* __restrict__ sc,
    const int* __restrict__ qz, __half* __restrict__ wt) {
    __shared__ __half s[64][136];

    const int tid = threadIdx.x;
    const int n_local = tid & 63;
    const int r0 = tid >> 6;
    const int n0 = blockIdx.x * 64;
    const int k20 = blockIdx.y * 64;
    const int n = n0 + n_local;

    const int g = k20 >> 6;  // GROUP_SIZE=128 -> 64 k2-rows per group
    const float sf = sc[(size_t)g * NTOT + n];
    const int zq = qz[(size_t)(g >> 1) * NTOT + n];
    const int z = (zq >> ((g & 1) * 4)) & 15;

#pragma unroll
    for (int i = 0; i < 16; i++) {
        const int k2r = i * 4 + r0;
        const int q = qw[(size_t)(k20 + k2r) * NTOT + n];
        s[n_local][2 * k2r]     = __float2half_rn((float)((q & 15) - z) * sf);
        s[n_local][2 * k2r + 1] = __float2half_rn((float)(((q >> 4) & 15) - z) * sf);
    }
    __syncthreads();

#pragma unroll
    for (int it = 0; it < 4; it++) {
        const int idx = it * 256 + tid;
        const int r = idx >> 4;
        const int c = idx & 15;
        uint4 v = *reinterpret_cast<const uint4*>(&s[r][c * 8]);
        *reinterpret_cast<uint4*>(
            &wt[(size_t)(n0 + r) * KTOT + 2 * k20 + c * 8]) = v;
    }
}

// ---------------------------------------------------------------------------
// Kernel 2: TMA + mma.sync pipelined GEMM. 128x128 tile, BK=64, 6 stages.
// Warps 0-7 compute (4x2 warp grid, 32x64 each); warp 8 = TMA producer.
// ---------------------------------------------------------------------------
__global__ void __launch_bounds__(288, 1) int4gemm_kernel(
    const __grid_constant__ CUtensorMap tma_a,
    const __grid_constant__ CUtensorMap tma_b,
    float* __restrict__ out) {
    extern __shared__ __align__(1024) char smem[];
    const uint32_t sb = smem_u32(smem);
    const int tid = threadIdx.x;
    const int wid = tid >> 5;
    const int l = tid & 31;

    const int m0 = blockIdx.y * BM;
    const int n0 = blockIdx.x * BN;

    if (tid == 0) {
#pragma unroll
        for (int s = 0; s < STAGES; s++) {
            mbar_init(sb + OFF_FULL + 8 * s, 1);   // tx-based completion
            mbar_init(sb + OFF_EMPTY + 8 * s, 8);  // 8 consumer warps
        }
        asm volatile("fence.mbarrier_init.release.cluster;" ::: "memory");
    }
    __syncthreads();

    if (wid == 8) {
        // ---- producer ----
        if (l == 0) {
            int s = 0, pe = 1;  // fresh barrier: wait(parity=1) passes immediately
            for (int kt = 0; kt < KTILES; kt++) {
                mbar_wait(sb + OFF_EMPTY + 8 * s, pe);
                mbar_expect_tx(sb + OFF_FULL + 8 * s, A_ST_BYTES + B_ST_BYTES);
                tma_load_2d(sb + OFF_A + s * A_ST_BYTES, (const void*)&tma_a,
                            kt * BK, m0, sb + OFF_FULL + 8 * s);
                tma_load_2d(sb + OFF_B + s * B_ST_BYTES, (const void*)&tma_b,
                            kt * BK, n0, sb + OFF_FULL + 8 * s);
                if (++s == STAGES) { s = 0; pe ^= 1; }
            }
        }
        return;
    }

    // ---- consumers ----
    const int wm = wid & 3;   // m offset 32*wm
    const int wn = wid >> 2;  // n offset 64*wn

    // ldmatrix lane addressing (SW128 swizzle: chunk ^ ((row&7)<<4), 128B rows)
    const uint32_t rowA = wm * 32 + (l & 15);
    const uint32_t xorA = (rowA & 7) << 4;
    const uint32_t colA = (l >> 4) * 16;
    const uint32_t aOff = rowA * 128;

    const uint32_t rowB = wn * 64 + (l & 7) + ((l >> 4) & 1) * 8;
    const uint32_t xorB = (l & 7) << 4;
    const uint32_t colB = ((l >> 3) & 1) * 16;
    const uint32_t bOff = rowB * 128;

    float c[2][8][4];
#pragma unroll
    for (int mt = 0; mt < 2; mt++)
#pragma unroll
        for (int nt = 0; nt < 8; nt++)
#pragma unroll
            for (int i = 0; i < 4; i++) c[mt][nt][i] = 0.0f;

    int s = 0, pf = 0;
    for (int kt = 0; kt < KTILES; kt++) {
        mbar_wait(sb + OFF_FULL + 8 * s, pf);
        const uint32_t aB = sb + OFF_A + s * A_ST_BYTES;
        const uint32_t bB = sb + OFF_B + s * B_ST_BYTES;

#pragma unroll
        for (int ks = 0; ks < BK / 16; ks++) {
            uint32_t a[2][4];
            uint32_t b[8][2];
#pragma unroll
            for (int mt = 0; mt < 2; mt++)
                ldsm_x4(a[mt][0], a[mt][1], a[mt][2], a[mt][3],
                        aB + aOff + mt * 2048 + ((ks * 32 + colA) ^ xorA));
#pragma unroll
            for (int np = 0; np < 4; np++) {
                uint32_t r0, r1, r2, r3;
                ldsm_x4(r0, r1, r2, r3,
                        bB + bOff + np * 2048 + ((ks * 32 + colB) ^ xorB));
                b[2 * np][0] = r0; b[2 * np][1] = r1;
                b[2 * np + 1][0] = r2; b[2 * np + 1][1] = r3;
            }
            if (ks == BK / 16 - 1) {
                if (l == 0) mbar_arrive(sb + OFF_EMPTY + 8 * s);
            }
#pragma unroll
            for (int mt = 0; mt < 2; mt++)
#pragma unroll
                for (int nt = 0; nt < 8; nt++)
                    mma16816(c[mt][nt], a[mt], b[nt]);
        }
        if (++s == STAGES) { s = 0; pf ^= 1; }
    }

    // ---- epilogue: regs -> f32 GMEM ----
    const int mb = m0 + wm * 32;
    const int nb = n0 + wn * 64;
    const int rq = l >> 2;
    const int cq = (l & 3) * 2;
#pragma unroll
    for (int mt = 0; mt < 2; mt++) {
#pragma unroll
        for (int nt = 0; nt < 8; nt++) {
            const size_t row = (size_t)(mb + mt * 16 + rq);
            const size_t col = (size_t)(nb + nt * 8 + cq);
            *reinterpret_cast<float2*>(&out[row * NTOT + col]) =
                make_float2(c[mt][nt][0], c[mt][nt][1]);
            *reinterpret_cast<float2*>(&out[(row + 8) * NTOT + col]) =
                make_float2(c[mt][nt][2], c[mt][nt][3]);
        }
    }
}

// ---------------------------------------------------------------------------
// host side
// ---------------------------------------------------------------------------
typedef CUresult (*PFN_encodeTiled)(
    CUtensorMap*, CUtensorMapDataType, cuuint32_t, void*,
    const cuuint64_t*, const cuuint64_t*, const cuuint32_t*, const cuuint32_t*,
    CUtensorMapInterleave, CUtensorMapSwizzle, CUtensorMapL2promotion,
    CUtensorMapFloatOOBfill);

static void encode_2d_f16(PFN_encodeTiled enc, CUtensorMap* m, void* ptr,
                          uint64_t d0, uint64_t d1, uint32_t b0, uint32_t b1) {
    cuuint64_t dims[2] = {d0, d1};
    cuuint64_t strides[1] = {d0 * 2};
    cuuint32_t box[2] = {b0, b1};
    cuuint32_t es[2] = {1, 1};
    enc(m, CU_TENSOR_MAP_DATA_TYPE_FLOAT16, 2, ptr, dims, strides, box, es,
        CU_TENSOR_MAP_INTERLEAVE_NONE, CU_TENSOR_MAP_SWIZZLE_128B,
        CU_TENSOR_MAP_L2_PROMOTION_L2_128B, CU_TENSOR_MAP_FLOAT_OOB_FILL_NONE);
}

extern "C" void kernel_launch(void* const* d_in, const int* in_sizes, int n_in,
                              void* d_out, int out_size) {
    const float* x = (const float*)d_in[0];
    const int* qw = (const int*)d_in[1];
    const float* sc = (const float*)d_in[2];
    const int* qz = (const int*)d_in[3];
    float* out = (float*)d_out;

    void* wt = nullptr;
    cudaGetSymbolAddress(&wt, g_Wt);
    void* xh = nullptr;
    cudaGetSymbolAddress(&xh, g_xh);

    // 0) x f32 -> f16
    convert_kernel<<<(MTOT * (size_t)KTOT) / (256 * 4), 256>>>(
        (const float4*)x, (__half*)xh);

    // 1) dequant + transpose into g_Wt[N][K]
    dequant_kernel<<<dim3(NTOT / 64, K2TOT / 64), 256>>>(qw, sc, qz, (__half*)wt);

    // 2) tensor maps
    PFN_encodeTiled enc = nullptr;
    cudaDriverEntryPointQueryResult qr;
    cudaGetDriverEntryPointByVersion("cuTensorMapEncodeTiled", (void**)&enc,
                                     12000, cudaEnableDefault, &qr);

    CUtensorMap map_a, map_b;
    encode_2d_f16(enc, &map_a, xh, KTOT, MTOT, BK, BM);   // xh[M,K] f16
    encode_2d_f16(enc, &map_b, wt, KTOT, NTOT, BK, BN);   // Wt[N,K] f16

    cudaFuncSetAttribute(int4gemm_kernel,
                         cudaFuncAttributeMaxDynamicSharedMemorySize, SMEM_TOTAL);

    int4gemm_kernel<<<dim3(NTOT / BN, MTOT / BM), 288, SMEM_TOTAL>>>(map_a, map_b, out);
}